// round 7
// baseline (speedup 1.0000x reference)
#include <cuda_runtime.h>
#include <cuda_bf16.h>
#include <cstdint>

#define TSTEPS 60
#define HDIM   50
#define BLOCK  256
#define ELPB   128
#define GRID   128
#define NTR    25                 // real n-tiles (25*8 = 200 gate cols)

// ---- smem byte layout ----
#define ABASE  0
#define ABUF   32768               // per buffer: 2 splits x 8 mt x 4 kt x 512B
#define ASPL   16384               // split stride inside a buffer
#define BBASE  (2 * ABUF)          // 65536
#define BSPL   (NTR * 1024)        // 25600 per split
#define XBASE  (BBASE + 2 * BSPL)  // 116736
#define WLBASE (XBASE + ELPB * 61 * 4)      // 147968
#define SMTOT  (WLBASE + TSTEPS * HDIM * 4) // 159968

__device__ __forceinline__ float ex2f(float x) {
    float r; asm("ex2.approx.f32 %0, %1;" : "=f"(r) : "f"(x)); return r;
}
__device__ __forceinline__ float rcpf(float x) {
    float r; asm("rcp.approx.f32 %0, %1;" : "=f"(r) : "f"(x)); return r;
}
__device__ __forceinline__ float sigf(float x) {
    return rcpf(1.0f + ex2f(-1.4426950408889634f * x));
}
__device__ __forceinline__ float tanhf_a(float x) {
    return fmaf(2.0f, rcpf(1.0f + ex2f(-2.8853900817779268f * x)), -1.0f);
}
__device__ __forceinline__ void mma16816(float* d, const uint32_t* a, const uint32_t* b) {
    asm volatile(
        "mma.sync.aligned.m16n8k16.row.col.f32.bf16.bf16.f32 "
        "{%0,%1,%2,%3}, {%4,%5,%6,%7}, {%8,%9}, {%0,%1,%2,%3};"
        : "+f"(d[0]), "+f"(d[1]), "+f"(d[2]), "+f"(d[3])
        : "r"(a[0]), "r"(a[1]), "r"(a[2]), "r"(a[3]), "r"(b[0]), "r"(b[1]));
}

// store A cols (k, k+1) for element row e (block-local) as bf16 hi+lo frags
__device__ __forceinline__ void store_apair(char* sm, int buf, int e, int k,
                                            float v0, float v1) {
    const int mt  = e >> 4, row = e & 15;
    const int kt  = k >> 4, kin = k & 15;
    const int tig = (kin >> 1) & 3;
    const int ridx = ((row >= 8) ? 1 : 0) + ((kin >= 8) ? 2 : 0);
    const int lt   = (row & 7) * 4 + tig;
    uint32_t hreg;
    asm("cvt.rn.bf16x2.f32 %0, %1, %2;" : "=r"(hreg) : "f"(v1), "f"(v0));
    const float b0 = __uint_as_float(hreg << 16);
    const float b1 = __uint_as_float(hreg & 0xffff0000u);
    uint32_t lreg;
    asm("cvt.rn.bf16x2.f32 %0, %1, %2;" : "=r"(lreg) : "f"(v1 - b1), "f"(v0 - b0));
    const int base = buf * ABUF + (mt * 4 + kt) * 512 + lt * 16 + ridx * 4;
    *(uint32_t*)(sm + ABASE + base)        = hreg;
    *(uint32_t*)(sm + ABASE + base + ASPL) = lreg;
}

__global__ void __launch_bounds__(BLOCK, 1)
lstm_wmma_kernel(const float* __restrict__ x_g,
                 const float* __restrict__ wih_g,
                 const float* __restrict__ whh_g,
                 const float* __restrict__ bih_g,
                 const float* __restrict__ bhh_g,
                 const float* __restrict__ wlin_g,
                 const float* __restrict__ blin_g,
                 float* __restrict__ out_g)
{
    extern __shared__ char sm[];
    const int tid  = threadIdx.x;
    const int lane = tid & 31;
    const int wid  = tid >> 5;

    // ---- zero both A buffers ----
    for (int i = tid; i < (2 * ABUF) / 16; i += BLOCK)
        ((uint4*)(sm + ABASE))[i] = make_uint4(0, 0, 0, 0);

    // ---- build B fragments: [s][nt][lane] = 4 uint2 (kt0..3) ----
    for (int idx = tid; idx < 2 * NTR * 4 * 32; idx += BLOCK) {
        const int s  = idx / (NTR * 4 * 32);
        int r        = idx % (NTR * 4 * 32);
        const int nt = r / 128;  r %= 128;
        const int kt = r / 32;
        const int ln = r % 32;
        const int bgr = ln >> 2, btig = ln & 3;
        const int n  = nt * 8 + bgr;                  // gate col (< 200)
        const int g  = n & 3, cell = n >> 2;
        const int row = (g == 0 ? 0 : g == 1 ? 50 : g == 2 ? 100 : 150) + cell;
        const int kk[4] = {kt * 16 + 2 * btig,     kt * 16 + 2 * btig + 1,
                           kt * 16 + 2 * btig + 8, kt * 16 + 2 * btig + 9};
        unsigned short v[4];
#pragma unroll
        for (int j = 0; j < 4; j++) {
            float w = 0.0f;
            const int k = kk[j];
            if (k < HDIM)     w = whh_g[row * HDIM + k];
            else if (k == 50) w = bih_g[row] + bhh_g[row];
            else if (k == 51) w = wih_g[row];
            const __nv_bfloat16 hi = __float2bfloat16(w);
            v[j] = (s == 0) ? __bfloat16_as_ushort(hi)
                            : __bfloat16_as_ushort(__float2bfloat16(w - __bfloat162float(hi)));
        }
        uint2 val;
        val.x = ((uint32_t)v[1] << 16) | v[0];
        val.y = ((uint32_t)v[3] << 16) | v[2];
        *(uint2*)(sm + BBASE + s * BSPL + nt * 1024 + ln * 32 + kt * 8) = val;
    }

    // ---- stage x and wlin ----
    {
        const float* xin = x_g + (size_t)blockIdx.x * ELPB * TSTEPS;
        for (int i = tid; i < ELPB * TSTEPS; i += BLOCK) {
            int el = i / TSTEPS, t = i % TSTEPS;
            ((float*)(sm + XBASE))[el * 61 + t] = xin[i];
        }
    }
    for (int i = tid; i < TSTEPS * HDIM; i += BLOCK)
        ((float*)(sm + WLBASE))[i] = wlin_g[i];
    __syncthreads();

    // A buf0 cols (50,51) = (1, x_0)
    if (tid < ELPB)
        store_apair(sm, 0, tid, 50, 1.0f, ((float*)(sm + XBASE))[tid * 61]);
    __syncthreads();

    // ---- per-lane roles (warp wid owns elements 16*wid .. 16*wid+15) ----
    const int gr  = lane >> 2;
    const int tig = lane & 3;
    const bool oddt = (tig & 1);
    const int eRow = wid * 16 + gr + (oddt ? 8 : 0);   // block-local element

    float cst[NTR];
#pragma unroll
    for (int i = 0; i < NTR; i++) cst[i] = 0.0f;
    float acc = 0.0f;

    const float* xs = (const float*)(sm + XBASE);

    for (int t = 0; t < TSTEPS; t++) {
        const int cur = t & 1, nxt = cur ^ 1;

        // load this warp's A fragments (step-constant)
        uint32_t aH[4][4], aL[4][4];
        const char* ab = sm + ABASE + cur * ABUF + (wid * 4) * 512 + lane * 16;
#pragma unroll
        for (int kt = 0; kt < 4; kt++) {
            *(uint4*)aH[kt] = *(const uint4*)(ab + kt * 512);
            *(uint4*)aL[kt] = *(const uint4*)(ab + kt * 512 + ASPL);
        }

        const float* wl = (const float*)(sm + WLBASE) + t * HDIM;

#pragma unroll
        for (int nt = 0; nt < NTR; nt++) {
            uint32_t bh[8], bl[8];
            const char* bb = sm + BBASE + nt * 1024 + lane * 32;
            *(uint4*)bh       = *(const uint4*)bb;
            *(uint4*)(bh + 4) = *(const uint4*)(bb + 16);
            *(uint4*)bl       = *(const uint4*)(bb + BSPL);
            *(uint4*)(bl + 4) = *(const uint4*)(bb + BSPL + 16);

            float dhh[4] = {0, 0, 0, 0}, dhl[4] = {0, 0, 0, 0}, dlh[4] = {0, 0, 0, 0};
#pragma unroll
            for (int kt = 0; kt < 4; kt++) {
                mma16816(dhh, aH[kt], bh + 2 * kt);
                mma16816(dhl, aH[kt], bl + 2 * kt);
                mma16816(dlh, aL[kt], bh + 2 * kt);
            }
            const float s0 = dhh[0] + dhl[0] + dlh[0];
            const float s1 = dhh[1] + dhl[1] + dlh[1];
            const float s2 = dhh[2] + dhl[2] + dlh[2];
            const float s3 = dhh[3] + dhl[3] + dlh[3];

            // regroup: each lane gets all 4 gates of one (row, cell)
            const float send0 = oddt ? s0 : s2;
            const float send1 = oddt ? s1 : s3;
            const float r0 = __shfl_xor_sync(0xffffffffu, send0, 1);
            const float r1 = __shfl_xor_sync(0xffffffffu, send1, 1);
            const float gi = oddt ? r0 : s0;
            const float gf = oddt ? r1 : s1;
            const float gg = oddt ? s2 : r0;
            const float go = oddt ? s3 : r1;

            const float ig = sigf(gi), fg = sigf(gf);
            const float gc = tanhf_a(gg), og = sigf(go);
            cst[nt] = fmaf(fg, cst[nt], ig * gc);
            const float hv = og * tanhf_a(cst[nt]);

            acc = fmaf(hv, wl[2 * nt + (tig >> 1)], acc);

            // pair even+odd cell h values (tig0/1 <- tig2/3, same row)
            const float hO = __shfl_xor_sync(0xffffffffu, hv, 2);
            if (tig < 2)
                store_apair(sm, nxt, eRow, 2 * nt, hv, hO);
        }

        // refresh (1, x_{t+1}) in the next buffer (tig2: row gr, tig3: row gr+8)
        if (tig >= 2)
            store_apair(sm, nxt, eRow, 50, 1.0f, xs[eRow * 61 + t + 1]);

        __syncwarp();
    }

    // reduce even/odd cell partials and write
    acc += __shfl_xor_sync(0xffffffffu, acc, 2);
    if (tig < 2)
        out_g[(size_t)blockIdx.x * ELPB + eRow] = acc + blin_g[0];
}

extern "C" void kernel_launch(void* const* d_in, const int* in_sizes, int n_in,
                              void* d_out, int out_size)
{
    const float* x    = (const float*)d_in[0];
    const float* wih  = (const float*)d_in[1];
    const float* whh  = (const float*)d_in[2];
    const float* bih  = (const float*)d_in[3];
    const float* bhh  = (const float*)d_in[4];
    const float* wlin = (const float*)d_in[5];
    const float* blin = (const float*)d_in[6];
    float* out = (float*)d_out;

    cudaFuncSetAttribute(lstm_wmma_kernel,
                         cudaFuncAttributeMaxDynamicSharedMemorySize, SMTOT);
    lstm_wmma_kernel<<<GRID, BLOCK, SMTOT>>>(x, wih, whh, bih, bhh, wlin, blin, out);
}

// round 8
// speedup vs baseline: 1.2928x; 1.2928x over previous
#include <cuda_runtime.h>
#include <cuda_bf16.h>
#include <cstdint>

#define TSTEPS 60
#define HDIM   50
#define BLOCK  512
#define ELPB   128
#define GRID   128
#define NTR    25                 // n-tiles of 8 gate cols (25*8 = 200)

// ---- smem byte layout ----
#define ABASE  0
#define ABUF   32768               // per buffer: 2 splits x 8 mt x 4 kt x 512B
#define ASPL   16384
#define BBASE  (2 * ABUF)          // 65536
#define BSPL   (NTR * 1024)        // 25600 per split
#define XBASE  (BBASE + 2 * BSPL)  // 116736
#define WLBASE (XBASE + ELPB * 61 * 4)       // 147968
#define OPBASE (WLBASE + TSTEPS * HDIM * 4)  // 159968
#define SMTOT  (OPBASE + ELPB * 4)           // 160480

__device__ __forceinline__ float ex2f(float x) {
    float r; asm("ex2.approx.f32 %0, %1;" : "=f"(r) : "f"(x)); return r;
}
__device__ __forceinline__ float rcpf(float x) {
    float r; asm("rcp.approx.f32 %0, %1;" : "=f"(r) : "f"(x)); return r;
}
__device__ __forceinline__ float sigf(float x) {
    return rcpf(1.0f + ex2f(-1.4426950408889634f * x));
}
__device__ __forceinline__ float tanhf_a(float x) {
    return fmaf(2.0f, rcpf(1.0f + ex2f(-2.8853900817779268f * x)), -1.0f);
}
__device__ __forceinline__ void mma16816(float* d, const uint32_t* a, const uint32_t* b) {
    asm volatile(
        "mma.sync.aligned.m16n8k16.row.col.f32.bf16.bf16.f32 "
        "{%0,%1,%2,%3}, {%4,%5,%6,%7}, {%8,%9}, {%0,%1,%2,%3};"
        : "+f"(d[0]), "+f"(d[1]), "+f"(d[2]), "+f"(d[3])
        : "r"(a[0]), "r"(a[1]), "r"(a[2]), "r"(a[3]), "r"(b[0]), "r"(b[1]));
}
__device__ __forceinline__ void barpair(int id) {
    asm volatile("bar.sync %0, 64;" :: "r"(id) : "memory");
}

// store A cols (k, k+1) for block-local element row e as bf16 hi+lo frags
__device__ __forceinline__ void store_apair(char* sm, int buf, int e, int k,
                                            float v0, float v1) {
    const int mt  = e >> 4, row = e & 15;
    const int kt  = k >> 4, kin = k & 15;
    const int tig = (kin >> 1) & 3;
    const int ridx = ((row >= 8) ? 1 : 0) + ((kin >= 8) ? 2 : 0);
    const int lt   = (row & 7) * 4 + tig;
    uint32_t hreg;
    asm("cvt.rn.bf16x2.f32 %0, %1, %2;" : "=r"(hreg) : "f"(v1), "f"(v0));
    const float b0 = __uint_as_float(hreg << 16);
    const float b1 = __uint_as_float(hreg & 0xffff0000u);
    uint32_t lreg;
    asm("cvt.rn.bf16x2.f32 %0, %1, %2;" : "=r"(lreg) : "f"(v1 - b1), "f"(v0 - b0));
    const int base = buf * ABUF + (mt * 4 + kt) * 512 + lt * 16 + ridx * 4;
    *(uint32_t*)(sm + ABASE + base)        = hreg;
    *(uint32_t*)(sm + ABASE + base + ASPL) = lreg;
}

__global__ void __launch_bounds__(BLOCK, 1)
lstm_pairw_kernel(const float* __restrict__ x_g,
                  const float* __restrict__ wih_g,
                  const float* __restrict__ whh_g,
                  const float* __restrict__ bih_g,
                  const float* __restrict__ bhh_g,
                  const float* __restrict__ wlin_g,
                  const float* __restrict__ blin_g,
                  float* __restrict__ out_g)
{
    extern __shared__ char sm[];
    const int tid  = threadIdx.x;
    const int lane = tid & 31;
    const int wid  = tid >> 5;
    const int mtile = wid >> 1;         // 0..7, 16 elements each
    const int half  = wid & 1;          // 0: nt 0..12, 1: nt 13..24

    // ---- zero both A buffers ----
    for (int i = tid; i < (2 * ABUF) / 16; i += BLOCK)
        ((uint4*)(sm + ABASE))[i] = make_uint4(0, 0, 0, 0);

    // ---- build B fragments: [s][nt][lane] = 4 uint2 (kt0..3) ----
    for (int idx = tid; idx < 2 * NTR * 4 * 32; idx += BLOCK) {
        const int s  = idx / (NTR * 4 * 32);
        int r        = idx % (NTR * 4 * 32);
        const int nt = r / 128;  r %= 128;
        const int kt = r / 32;
        const int ln = r % 32;
        const int bgr = ln >> 2, btig = ln & 3;
        const int n  = nt * 8 + bgr;
        const int g  = n & 3, cell = n >> 2;
        const int row = (g == 0 ? 0 : g == 1 ? 50 : g == 2 ? 100 : 150) + cell;
        const int kk[4] = {kt * 16 + 2 * btig,     kt * 16 + 2 * btig + 1,
                           kt * 16 + 2 * btig + 8, kt * 16 + 2 * btig + 9};
        unsigned short v[4];
#pragma unroll
        for (int j = 0; j < 4; j++) {
            float w = 0.0f;
            const int k = kk[j];
            if (k < HDIM)     w = whh_g[row * HDIM + k];
            else if (k == 50) w = bih_g[row] + bhh_g[row];
            else if (k == 51) w = wih_g[row];
            const __nv_bfloat16 hi = __float2bfloat16(w);
            v[j] = (s == 0) ? __bfloat16_as_ushort(hi)
                            : __bfloat16_as_ushort(__float2bfloat16(w - __bfloat162float(hi)));
        }
        uint2 val;
        val.x = ((uint32_t)v[1] << 16) | v[0];
        val.y = ((uint32_t)v[3] << 16) | v[2];
        *(uint2*)(sm + BBASE + s * BSPL + nt * 1024 + ln * 32 + kt * 8) = val;
    }

    // ---- stage x and wlin ----
    {
        const float* xin = x_g + (size_t)blockIdx.x * ELPB * TSTEPS;
        for (int i = tid; i < ELPB * TSTEPS; i += BLOCK) {
            int el = i / TSTEPS, t = i % TSTEPS;
            ((float*)(sm + XBASE))[el * 61 + t] = xin[i];
        }
    }
    for (int i = tid; i < TSTEPS * HDIM; i += BLOCK)
        ((float*)(sm + WLBASE))[i] = wlin_g[i];
    __syncthreads();

    if (tid < ELPB)
        store_apair(sm, 0, tid, 50, 1.0f, ((float*)(sm + XBASE))[tid * 61]);
    __syncthreads();

    // ---- lane roles within the mtile ----
    const int gr  = lane >> 2;
    const int tig = lane & 3;
    const bool oddt = (tig & 1);
    const int eRow = mtile * 16 + gr + (oddt ? 8 : 0);

    const int ntLo = half ? 13 : 0;
    const int ntHi = half ? 25 : 13;
    const int barid = 1 + mtile;

    float cst[13];
#pragma unroll
    for (int i = 0; i < 13; i++) cst[i] = 0.0f;
    float acc = 0.0f;

    const float* xs = (const float*)(sm + XBASE);

    for (int t = 0; t < TSTEPS; t++) {
        const int cur = t & 1, nxt = cur ^ 1;

        uint32_t aH[4][4], aL[4][4];
        const char* ab = sm + ABASE + cur * ABUF + (mtile * 4) * 512 + lane * 16;
#pragma unroll
        for (int kt = 0; kt < 4; kt++) {
            *(uint4*)aH[kt] = *(const uint4*)(ab + kt * 512);
            *(uint4*)aL[kt] = *(const uint4*)(ab + kt * 512 + ASPL);
        }

        const float* wl = (const float*)(sm + WLBASE) + t * HDIM;

#pragma unroll
        for (int nn = 0; nn < 13; nn++) {
            const int nt = ntLo + nn;
            if (nt >= ntHi) break;

            uint32_t bh[8], bl[8];
            const char* bb = sm + BBASE + nt * 1024 + lane * 32;
            *(uint4*)bh       = *(const uint4*)bb;
            *(uint4*)(bh + 4) = *(const uint4*)(bb + 16);
            *(uint4*)bl       = *(const uint4*)(bb + BSPL);
            *(uint4*)(bl + 4) = *(const uint4*)(bb + BSPL + 16);

            float dhh[4] = {0, 0, 0, 0}, dhl[4] = {0, 0, 0, 0}, dlh[4] = {0, 0, 0, 0};
#pragma unroll
            for (int kt = 0; kt < 4; kt++) {
                mma16816(dhh, aH[kt], bh + 2 * kt);
                mma16816(dhl, aH[kt], bl + 2 * kt);
                mma16816(dlh, aL[kt], bh + 2 * kt);
            }
            const float s0 = dhh[0] + dhl[0] + dlh[0];
            const float s1 = dhh[1] + dhl[1] + dlh[1];
            const float s2 = dhh[2] + dhl[2] + dlh[2];
            const float s3 = dhh[3] + dhl[3] + dlh[3];

            const float send0 = oddt ? s0 : s2;
            const float send1 = oddt ? s1 : s3;
            const float r0 = __shfl_xor_sync(0xffffffffu, send0, 1);
            const float r1 = __shfl_xor_sync(0xffffffffu, send1, 1);
            const float gi = oddt ? r0 : s0;
            const float gf = oddt ? r1 : s1;
            const float gg = oddt ? s2 : r0;
            const float go = oddt ? s3 : r1;

            const float ig = sigf(gi), fg = sigf(gf);
            const float gc = tanhf_a(gg), og = sigf(go);
            cst[nn] = fmaf(fg, cst[nn], ig * gc);
            const float hv = og * tanhf_a(cst[nn]);

            acc = fmaf(hv, wl[2 * nt + (tig >> 1)], acc);

            const float hO = __shfl_xor_sync(0xffffffffu, hv, 2);
            if (tig < 2)
                store_apair(sm, nxt, eRow, 2 * nt, hv, hO);
        }

        // refresh (1, x_{t+1}) in the next buffer (even warp, tig>=2 lanes)
        if (half == 0 && tig >= 2 && t + 1 < TSTEPS)
            store_apair(sm, nxt, eRow, 50, 1.0f, xs[eRow * 61 + t + 1]);

        barpair(barid);
    }

    // ---- pair reduction of output partials ----
    acc += __shfl_xor_sync(0xffffffffu, acc, 2);
    float* op = (float*)(sm + OPBASE);
    if (half == 0 && tig < 2) op[eRow] = acc;
    barpair(barid);
    if (half == 1 && tig < 2)
        out_g[(size_t)blockIdx.x * ELPB + eRow] = acc + op[eRow] + blin_g[0];
}

extern "C" void kernel_launch(void* const* d_in, const int* in_sizes, int n_in,
                              void* d_out, int out_size)
{
    const float* x    = (const float*)d_in[0];
    const float* wih  = (const float*)d_in[1];
    const float* whh  = (const float*)d_in[2];
    const float* bih  = (const float*)d_in[3];
    const float* bhh  = (const float*)d_in[4];
    const float* wlin = (const float*)d_in[5];
    const float* blin = (const float*)d_in[6];
    float* out = (float*)d_out;

    cudaFuncSetAttribute(lstm_pairw_kernel,
                         cudaFuncAttributeMaxDynamicSharedMemorySize, SMTOT);
    lstm_pairw_kernel<<<GRID, BLOCK, SMTOT>>>(x, wih, whh, bih, bhh, wlin, blin, out);
}

// round 9
// speedup vs baseline: 1.7199x; 1.3303x over previous
#include <cuda_runtime.h>
#include <cuda_fp16.h>
#include <cstdint>

#define TSTEPS 60
#define HDIM   50
#define BLOCK  512
#define ELPB   128
#define GRID   128
#define NTR    25                 // n-tiles of 8 gate cols (25*8 = 200)

// ---- smem byte layout ----
#define ABASE  0
#define ABUF   16384               // per buffer: 8 mt x 4 kt x 512B (fp16)
#define BBASE  (2 * ABUF)          // 32768
#define BSPL   (NTR * 1024)        // 25600 per split (hi, lo)
#define XBASE  (BBASE + 2 * BSPL)  // 83968
#define WLBASE (XBASE + ELPB * 61 * 4)       // 115200
#define OPBASE (WLBASE + TSTEPS * HDIM * 4)  // 127200
#define SMTOT  (OPBASE + ELPB * 4)           // 127712

__device__ __forceinline__ float ex2f(float x) {
    float r; asm("ex2.approx.f32 %0, %1;" : "=f"(r) : "f"(x)); return r;
}
__device__ __forceinline__ float rcpf(float x) {
    float r; asm("rcp.approx.f32 %0, %1;" : "=f"(r) : "f"(x)); return r;
}
__device__ __forceinline__ float sigf(float x) {
    return rcpf(1.0f + ex2f(-1.4426950408889634f * x));
}
__device__ __forceinline__ float tanhf_a(float x) {
    return fmaf(2.0f, rcpf(1.0f + ex2f(-2.8853900817779268f * x)), -1.0f);
}
__device__ __forceinline__ void mma16816h(float* d, const uint32_t* a, const uint32_t* b) {
    asm volatile(
        "mma.sync.aligned.m16n8k16.row.col.f32.f16.f16.f32 "
        "{%0,%1,%2,%3}, {%4,%5,%6,%7}, {%8,%9}, {%0,%1,%2,%3};"
        : "+f"(d[0]), "+f"(d[1]), "+f"(d[2]), "+f"(d[3])
        : "r"(a[0]), "r"(a[1]), "r"(a[2]), "r"(a[3]), "r"(b[0]), "r"(b[1]));
}
__device__ __forceinline__ void barpair(int id) {
    asm volatile("bar.sync %0, 64;" :: "r"(id) : "memory");
}

// store A cols (k, k+1) for block-local element row e as one f16x2
__device__ __forceinline__ void store_ah(char* sm, int buf, int e, int k,
                                         float v0, float v1) {
    const int mt  = e >> 4, row = e & 15;
    const int kt  = k >> 4, kin = k & 15;
    const int tig = (kin >> 1) & 3;
    const int ridx = ((row >= 8) ? 1 : 0) + ((kin >= 8) ? 2 : 0);
    const int lt   = (row & 7) * 4 + tig;
    uint32_t hreg;
    asm("cvt.rn.f16x2.f32 %0, %1, %2;" : "=r"(hreg) : "f"(v1), "f"(v0));
    const int base = buf * ABUF + (mt * 4 + kt) * 512 + lt * 16 + ridx * 4;
    *(uint32_t*)(sm + ABASE + base) = hreg;
}

__global__ void __launch_bounds__(BLOCK, 1)
lstm_fp16_kernel(const float* __restrict__ x_g,
                 const float* __restrict__ wih_g,
                 const float* __restrict__ whh_g,
                 const float* __restrict__ bih_g,
                 const float* __restrict__ bhh_g,
                 const float* __restrict__ wlin_g,
                 const float* __restrict__ blin_g,
                 float* __restrict__ out_g)
{
    extern __shared__ char sm[];
    const int tid  = threadIdx.x;
    const int lane = tid & 31;
    const int wid  = tid >> 5;
    const int mtile = wid >> 1;         // 0..7, 16 elements each
    const int half  = wid & 1;          // 0: nt 0..12, 1: nt 13..24

    // ---- zero both A buffers ----
    for (int i = tid; i < (2 * ABUF) / 16; i += BLOCK)
        ((uint4*)(sm + ABASE))[i] = make_uint4(0, 0, 0, 0);

    // ---- build B fragments (fp16 hi+lo), contiguous per (nt, ktpair) ----
    // entry: [s][nt][kt2][lane] = uint4 {kt=2kt2: (b0,b1), kt=2kt2+1: (b0,b1)}
    for (int idx = tid; idx < 2 * NTR * 2 * 32; idx += BLOCK) {
        const int s   = idx / (NTR * 2 * 32);
        int r         = idx % (NTR * 2 * 32);
        const int nt  = r / 64;  r %= 64;
        const int kt2 = r / 32;
        const int ln  = r % 32;
        const int bgr = ln >> 2, btig = ln & 3;
        const int n   = nt * 8 + bgr;
        const int g   = n & 3, cell = n >> 2;
        const int row = (g == 0 ? 0 : g == 1 ? 50 : g == 2 ? 100 : 150) + cell;
        uint32_t u[4];
#pragma unroll
        for (int ktl = 0; ktl < 2; ktl++) {
            const int kt = 2 * kt2 + ktl;
            const int kk[4] = {kt * 16 + 2 * btig,     kt * 16 + 2 * btig + 1,
                               kt * 16 + 2 * btig + 8, kt * 16 + 2 * btig + 9};
            unsigned short v[4];
#pragma unroll
            for (int j = 0; j < 4; j++) {
                float w = 0.0f;
                const int k = kk[j];
                if (k < HDIM)     w = whh_g[row * HDIM + k];
                else if (k == 50) w = bih_g[row] + bhh_g[row];
                else if (k == 51) w = wih_g[row];
                const __half hi = __float2half_rn(w);
                v[j] = (s == 0) ? __half_as_ushort(hi)
                                : __half_as_ushort(__float2half_rn(w - __half2float(hi)));
            }
            u[2 * ktl]     = ((uint32_t)v[1] << 16) | v[0];
            u[2 * ktl + 1] = ((uint32_t)v[3] << 16) | v[2];
        }
        *(uint4*)(sm + BBASE + s * BSPL + nt * 1024 + kt2 * 512 + ln * 16) =
            make_uint4(u[0], u[1], u[2], u[3]);
    }

    // ---- stage x and wlin ----
    {
        const float* xin = x_g + (size_t)blockIdx.x * ELPB * TSTEPS;
        for (int i = tid; i < ELPB * TSTEPS; i += BLOCK) {
            int el = i / TSTEPS, t = i % TSTEPS;
            ((float*)(sm + XBASE))[el * 61 + t] = xin[i];
        }
    }
    for (int i = tid; i < TSTEPS * HDIM; i += BLOCK)
        ((float*)(sm + WLBASE))[i] = wlin_g[i];
    __syncthreads();

    if (tid < ELPB)
        store_ah(sm, 0, tid, 50, 1.0f, ((float*)(sm + XBASE))[tid * 61]);
    __syncthreads();

    // ---- lane roles within the mtile ----
    const int gr  = lane >> 2;
    const int tig = lane & 3;
    const bool oddt = (tig & 1);
    const int eRow = mtile * 16 + gr + (oddt ? 8 : 0);

    const int ntLo = half ? 13 : 0;
    const int ntHi = half ? 25 : 13;
    const int barid = 1 + mtile;

    float cst[13];
#pragma unroll
    for (int i = 0; i < 13; i++) cst[i] = 0.0f;
    float acc = 0.0f;

    const float* xs = (const float*)(sm + XBASE);

    for (int t = 0; t < TSTEPS; t++) {
        const int cur = t & 1, nxt = cur ^ 1;

        // A fragments (single fp16 copy), step-constant per warp
        uint32_t aH[4][4];
        const char* ab = sm + ABASE + cur * ABUF + (mtile * 4) * 512 + lane * 16;
#pragma unroll
        for (int kt = 0; kt < 4; kt++)
            *(uint4*)aH[kt] = *(const uint4*)(ab + kt * 512);

        const float* wl = (const float*)(sm + WLBASE) + t * HDIM;

#pragma unroll
        for (int nn = 0; nn < 13; nn++) {
            const int nt = ntLo + nn;
            if (nt >= ntHi) break;

            uint32_t bh[8], bl[8];
            const char* bb = sm + BBASE + nt * 1024 + lane * 16;
            *(uint4*)bh       = *(const uint4*)bb;
            *(uint4*)(bh + 4) = *(const uint4*)(bb + 512);
            *(uint4*)bl       = *(const uint4*)(bb + BSPL);
            *(uint4*)(bl + 4) = *(const uint4*)(bb + BSPL + 512);

            float d1[4] = {0, 0, 0, 0}, d2[4] = {0, 0, 0, 0};
#pragma unroll
            for (int kt = 0; kt < 4; kt++) {
                mma16816h(d1, aH[kt], bh + 2 * kt);
                mma16816h(d2, aH[kt], bl + 2 * kt);
            }
            const float s0 = d1[0] + d2[0];
            const float s1 = d1[1] + d2[1];
            const float s2 = d1[2] + d2[2];
            const float s3 = d1[3] + d2[3];

            // regroup: each lane gets all 4 gates of one (row, cell)
            const float send0 = oddt ? s0 : s2;
            const float send1 = oddt ? s1 : s3;
            const float r0 = __shfl_xor_sync(0xffffffffu, send0, 1);
            const float r1 = __shfl_xor_sync(0xffffffffu, send1, 1);
            const float gi = oddt ? r0 : s0;
            const float gf = oddt ? r1 : s1;
            const float gg = oddt ? s2 : r0;
            const float go = oddt ? s3 : r1;

            const float ig = sigf(gi), fg = sigf(gf);
            const float gc = tanhf_a(gg), og = sigf(go);
            cst[nn] = fmaf(fg, cst[nn], ig * gc);
            const float hv = og * tanhf_a(cst[nn]);

            acc = fmaf(hv, wl[2 * nt + (tig >> 1)], acc);

            const float hO = __shfl_xor_sync(0xffffffffu, hv, 2);
            if (tig < 2)
                store_ah(sm, nxt, eRow, 2 * nt, hv, hO);
        }

        // refresh (1, x_{t+1}) in next buffer (even warp, tig>=2 lanes)
        if (half == 0 && tig >= 2 && t + 1 < TSTEPS)
            store_ah(sm, nxt, eRow, 50, 1.0f, xs[eRow * 61 + t + 1]);

        barpair(barid);
    }

    // ---- pair reduction of output partials ----
    acc += __shfl_xor_sync(0xffffffffu, acc, 2);
    float* op = (float*)(sm + OPBASE);
    if (half == 0 && tig < 2) op[eRow] = acc;
    barpair(barid);
    if (half == 1 && tig < 2)
        out_g[(size_t)blockIdx.x * ELPB + eRow] = acc + op[eRow] + blin_g[0];
}

extern "C" void kernel_launch(void* const* d_in, const int* in_sizes, int n_in,
                              void* d_out, int out_size)
{
    const float* x    = (const float*)d_in[0];
    const float* wih  = (const float*)d_in[1];
    const float* whh  = (const float*)d_in[2];
    const float* bih  = (const float*)d_in[3];
    const float* bhh  = (const float*)d_in[4];
    const float* wlin = (const float*)d_in[5];
    const float* blin = (const float*)d_in[6];
    float* out = (float*)d_out;

    cudaFuncSetAttribute(lstm_fp16_kernel,
                         cudaFuncAttributeMaxDynamicSharedMemorySize, SMTOT);
    lstm_fp16_kernel<<<GRID, BLOCK, SMTOT>>>(x, wih, whh, bih, bhh, wlin, blin, out);
}

// round 10
// speedup vs baseline: 2.6509x; 1.5413x over previous
#include <cuda_runtime.h>
#include <cuda_fp16.h>
#include <cstdint>

#define TSTEPS 60
#define HDIM   50
#define BLOCK  512
#define ELPB   128
#define GRID   128
#define NTT    26                 // n-tiles (13 pairs x 16 cols = 208)
#define NPAIR  13

// ---- smem byte layout ----
#define ABASE  0
#define ABUF   16384               // per buffer: 8 mt x 4 kt x 512B (fp16)
#define BBASE  (2 * ABUF)          // 32768
#define BSPL   (NTT * 1024)        // 26624 per split (hi, lo)
#define XBASE  (BBASE + 2 * BSPL)  // 86016
#define WLBASE (XBASE + ELPB * 61 * 4)       // 117248
#define OPBASE (WLBASE + TSTEPS * HDIM * 4)  // 129248
#define SMTOT  (OPBASE + ELPB * 4)           // 129760

__device__ __forceinline__ float tanha(float x) {
    float r; asm("tanh.approx.f32 %0, %1;" : "=f"(r) : "f"(x)); return r;
}
__device__ __forceinline__ float sigt(float x) {
    return fmaf(0.5f, tanha(0.5f * x), 0.5f);
}
__device__ __forceinline__ void mma16816h(float* d, const uint32_t* a, const uint32_t* b) {
    asm volatile(
        "mma.sync.aligned.m16n8k16.row.col.f32.f16.f16.f32 "
        "{%0,%1,%2,%3}, {%4,%5,%6,%7}, {%8,%9}, {%0,%1,%2,%3};"
        : "+f"(d[0]), "+f"(d[1]), "+f"(d[2]), "+f"(d[3])
        : "r"(a[0]), "r"(a[1]), "r"(a[2]), "r"(a[3]), "r"(b[0]), "r"(b[1]));
}
__device__ __forceinline__ void barpair(int id) {
    asm volatile("bar.sync %0, 64;" :: "r"(id) : "memory");
}

// store single f16 h value at (element row e, A col k)
__device__ __forceinline__ void store_h16(char* sm, int buf, int e, int k, float v) {
    const int mt  = e >> 4, row = e & 15;
    const int kt  = k >> 4, kin = k & 15;
    const int tg  = (kin >> 1) & 3;
    const int ridx = ((row >= 8) ? 1 : 0) + ((kin >= 8) ? 2 : 0);
    const int lt   = (row & 7) * 4 + tg;
    const int base = buf * ABUF + (mt * 4 + kt) * 512 + lt * 16 + ridx * 4 + (k & 1) * 2;
    *(__half*)(sm + ABASE + base) = __float2half_rn(v);
}
// store f16x2 pair at cols (k, k+1), k even
__device__ __forceinline__ void store_hpair(char* sm, int buf, int e, int k,
                                            float v0, float v1) {
    const int mt  = e >> 4, row = e & 15;
    const int kt  = k >> 4, kin = k & 15;
    const int tg  = (kin >> 1) & 3;
    const int ridx = ((row >= 8) ? 1 : 0) + ((kin >= 8) ? 2 : 0);
    const int lt   = (row & 7) * 4 + tg;
    uint32_t hreg;
    asm("cvt.rn.f16x2.f32 %0, %1, %2;" : "=r"(hreg) : "f"(v1), "f"(v0));
    const int base = buf * ABUF + (mt * 4 + kt) * 512 + lt * 16 + ridx * 4;
    *(uint32_t*)(sm + ABASE + base) = hreg;
}

__global__ void __launch_bounds__(BLOCK, 1)
lstm_ng_kernel(const float* __restrict__ x_g,
               const float* __restrict__ wih_g,
               const float* __restrict__ whh_g,
               const float* __restrict__ bih_g,
               const float* __restrict__ bhh_g,
               const float* __restrict__ wlin_g,
               const float* __restrict__ blin_g,
               float* __restrict__ out_g)
{
    extern __shared__ char sm[];
    const int tid  = threadIdx.x;
    const int lane = tid & 31;
    const int wid  = tid >> 5;
    const int mtile = wid >> 1;
    const int half  = wid & 1;

    // ---- zero both A buffers ----
    for (int i = tid; i < (2 * ABUF) / 16; i += BLOCK)
        ((uint4*)(sm + ABASE))[i] = make_uint4(0, 0, 0, 0);

    // ---- build B fragments (fp16 hi+lo) with gate-pair column order ----
    // nt even (pair p): cols = i,f of cells 4p..4p+3 ; nt odd: g,o
    for (int idx = tid; idx < 2 * NTT * 2 * 32; idx += BLOCK) {
        const int s   = idx / (NTT * 2 * 32);
        int r         = idx % (NTT * 2 * 32);
        const int nt  = r / 64;  r %= 64;
        const int kt2 = r / 32;
        const int ln  = r % 32;
        const int bgr = ln >> 2, btig = ln & 3;
        const int p    = nt >> 1, oddnt = nt & 1;
        const int u    = bgr >> 1, v = bgr & 1;
        const int cell = 4 * p + u;
        const int gate = oddnt ? (v ? 3 : 2) : (v ? 1 : 0);     // i,f,g,o
        const int grow = (gate == 0 ? 0 : gate == 1 ? 50 : gate == 2 ? 100 : 150);
        const int row  = grow + cell;
        const bool realc = (cell < HDIM);
        uint32_t u4[4];
#pragma unroll
        for (int ktl = 0; ktl < 2; ktl++) {
            const int kt = 2 * kt2 + ktl;
            const int kk[4] = {kt * 16 + 2 * btig,     kt * 16 + 2 * btig + 1,
                               kt * 16 + 2 * btig + 8, kt * 16 + 2 * btig + 9};
            unsigned short vv[4];
#pragma unroll
            for (int j = 0; j < 4; j++) {
                float w = 0.0f;
                const int k = kk[j];
                if (realc) {
                    if (k < HDIM)     w = whh_g[row * HDIM + k];
                    else if (k == 50) w = bih_g[row] + bhh_g[row];
                    else if (k == 51) w = wih_g[row];
                }
                const __half hi = __float2half_rn(w);
                vv[j] = (s == 0) ? __half_as_ushort(hi)
                                 : __half_as_ushort(__float2half_rn(w - __half2float(hi)));
            }
            u4[2 * ktl]     = ((uint32_t)vv[1] << 16) | vv[0];
            u4[2 * ktl + 1] = ((uint32_t)vv[3] << 16) | vv[2];
        }
        *(uint4*)(sm + BBASE + s * BSPL + nt * 1024 + kt2 * 512 + ln * 16) =
            make_uint4(u4[0], u4[1], u4[2], u4[3]);
    }

    // ---- stage x and wlin ----
    {
        const float* xin = x_g + (size_t)blockIdx.x * ELPB * TSTEPS;
        for (int i = tid; i < ELPB * TSTEPS; i += BLOCK) {
            int el = i / TSTEPS, t = i % TSTEPS;
            ((float*)(sm + XBASE))[el * 61 + t] = xin[i];
        }
    }
    for (int i = tid; i < TSTEPS * HDIM; i += BLOCK)
        ((float*)(sm + WLBASE))[i] = wlin_g[i];
    __syncthreads();

    if (tid < ELPB)
        store_hpair(sm, 0, tid, 50, 1.0f, ((float*)(sm + XBASE))[tid * 61]);
    __syncthreads();

    // ---- lane roles ----
    const int gr  = lane >> 2;           // row group 0..7
    const int tig = lane & 3;            // cell-in-quad
    const int eRow0 = mtile * 16 + gr;
    const int eRow1 = eRow0 + 8;
    const int pLo = half ? 7 : 0;
    const int pCnt = half ? 6 : 7;
    const int barid = 1 + mtile;

    float c0[7], c1[7];
#pragma unroll
    for (int i = 0; i < 7; i++) { c0[i] = 0.0f; c1[i] = 0.0f; }
    float acc0 = 0.0f, acc1 = 0.0f;

    const float* xs = (const float*)(sm + XBASE);

    for (int t = 0; t < TSTEPS; t++) {
        const int cur = t & 1, nxt = cur ^ 1;

        uint32_t aH[4][4];
        const char* ab = sm + ABASE + cur * ABUF + (mtile * 4) * 512 + lane * 16;
#pragma unroll
        for (int kt = 0; kt < 4; kt++)
            *(uint4*)aH[kt] = *(const uint4*)(ab + kt * 512);

        const float* wl = (const float*)(sm + WLBASE) + t * HDIM;

#pragma unroll
        for (int pp = 0; pp < 7; pp++) {
            if (pp >= pCnt) break;
            const int p    = pLo + pp;
            const int cell = 4 * p + tig;

            uint32_t bifh[8], bifl[8], bgoh[8], bgol[8];
            const char* bbE = sm + BBASE + (2 * p) * 1024 + lane * 16;
            *(uint4*)bifh       = *(const uint4*)bbE;
            *(uint4*)(bifh + 4) = *(const uint4*)(bbE + 512);
            *(uint4*)bifl       = *(const uint4*)(bbE + BSPL);
            *(uint4*)(bifl + 4) = *(const uint4*)(bbE + BSPL + 512);
            *(uint4*)bgoh       = *(const uint4*)(bbE + 1024);
            *(uint4*)(bgoh + 4) = *(const uint4*)(bbE + 1536);
            *(uint4*)bgol       = *(const uint4*)(bbE + BSPL + 1024);
            *(uint4*)(bgol + 4) = *(const uint4*)(bbE + BSPL + 1536);

            float dif[4] = {0, 0, 0, 0}, difl[4] = {0, 0, 0, 0};
            float dgo[4] = {0, 0, 0, 0}, dgol[4] = {0, 0, 0, 0};
#pragma unroll
            for (int kt = 0; kt < 4; kt++) {
                mma16816h(dif,  aH[kt], bifh + 2 * kt);
                mma16816h(difl, aH[kt], bifl + 2 * kt);
                mma16816h(dgo,  aH[kt], bgoh + 2 * kt);
                mma16816h(dgol, aH[kt], bgol + 2 * kt);
            }
            const float gi0 = dif[0] + difl[0], gf0 = dif[1] + difl[1];
            const float gi1 = dif[2] + difl[2], gf1 = dif[3] + difl[3];
            const float gg0 = dgo[0] + dgol[0], go0 = dgo[1] + dgol[1];
            const float gg1 = dgo[2] + dgol[2], go1 = dgo[3] + dgol[3];

            const float i0 = sigt(gi0), f0 = sigt(gf0), o0 = sigt(go0);
            const float g0 = tanha(gg0);
            c0[pp] = fmaf(f0, c0[pp], i0 * g0);
            const float h0 = o0 * tanha(c0[pp]);

            const float i1 = sigt(gi1), f1 = sigt(gf1), o1 = sigt(go1);
            const float g1 = tanha(gg1);
            c1[pp] = fmaf(f1, c1[pp], i1 * g1);
            const float h1 = o1 * tanha(c1[pp]);

            if (cell < HDIM) {
                const float wv = wl[cell];
                acc0 = fmaf(h0, wv, acc0);
                acc1 = fmaf(h1, wv, acc1);
                store_h16(sm, nxt, eRow0, cell, h0);
                store_h16(sm, nxt, eRow1, cell, h1);
            }
        }

        // refresh (1, x_{t+1}) in next buffer (odd-half warp, lanes 0..15)
        if (half == 1 && lane < 16 && t + 1 < TSTEPS) {
            const int er = mtile * 16 + lane;
            store_hpair(sm, nxt, er, 50, 1.0f, xs[er * 61 + t + 1]);
        }

        barpair(barid);
    }

    // ---- reductions: over tig within row group, then across warp pair ----
    acc0 += __shfl_xor_sync(0xffffffffu, acc0, 1);
    acc0 += __shfl_xor_sync(0xffffffffu, acc0, 2);
    acc1 += __shfl_xor_sync(0xffffffffu, acc1, 1);
    acc1 += __shfl_xor_sync(0xffffffffu, acc1, 2);

    float* op = (float*)(sm + OPBASE);
    if (half == 0 && tig == 0) {
        op[eRow0] = acc0;
        op[eRow1] = acc1;
    }
    barpair(barid);
    if (half == 1 && tig == 0) {
        const float b = blin_g[0];
        out_g[(size_t)blockIdx.x * ELPB + eRow0] = acc0 + op[eRow0] + b;
        out_g[(size_t)blockIdx.x * ELPB + eRow1] = acc1 + op[eRow1] + b;
    }
}

extern "C" void kernel_launch(void* const* d_in, const int* in_sizes, int n_in,
                              void* d_out, int out_size)
{
    const float* x    = (const float*)d_in[0];
    const float* wih  = (const float*)d_in[1];
    const float* whh  = (const float*)d_in[2];
    const float* bih  = (const float*)d_in[3];
    const float* bhh  = (const float*)d_in[4];
    const float* wlin = (const float*)d_in[5];
    const float* blin = (const float*)d_in[6];
    float* out = (float*)d_out;

    cudaFuncSetAttribute(lstm_ng_kernel,
                         cudaFuncAttributeMaxDynamicSharedMemorySize, SMTOT);
    lstm_ng_kernel<<<GRID, BLOCK, SMTOT>>>(x, wih, whh, bih, bhh, wlin, blin, out);
}

// round 11
// speedup vs baseline: 3.8415x; 1.4492x over previous
#include <cuda_runtime.h>
#include <cuda_fp16.h>
#include <cstdint>

#define TSTEPS 60
#define HDIM   50
#define BLOCK  512
#define ELPB   128
#define GRID   128
#define NTT    26                 // n-tiles (13 pairs x 16 gate cols)

// ---- smem byte layout ----
#define ABASE  0
#define ABUF   16384               // per buffer: 8 mt x 4 kt x 512B (fp16)
#define BBASE  (2 * ABUF)          // 32768  (single split, 26624 B)
#define XBASE  (BBASE + NTT * 1024)          // 59392
#define WLBASE (XBASE + ELPB * 61 * 4)       // 90624
#define OPBASE (WLBASE + TSTEPS * HDIM * 4)  // 102624
#define SMTOT  (OPBASE + 4 * ELPB * 4)       // 104672

__device__ __forceinline__ float tanha(float x) {
    float r; asm("tanh.approx.f32 %0, %1;" : "=f"(r) : "f"(x)); return r;
}
__device__ __forceinline__ float sigt(float x) {
    return fmaf(0.5f, tanha(0.5f * x), 0.5f);
}
__device__ __forceinline__ void mma16816h(float* d, const uint32_t* a, const uint32_t* b) {
    asm volatile(
        "mma.sync.aligned.m16n8k16.row.col.f32.f16.f16.f32 "
        "{%0,%1,%2,%3}, {%4,%5,%6,%7}, {%8,%9}, {%0,%1,%2,%3};"
        : "+f"(d[0]), "+f"(d[1]), "+f"(d[2]), "+f"(d[3])
        : "r"(a[0]), "r"(a[1]), "r"(a[2]), "r"(a[3]), "r"(b[0]), "r"(b[1]));
}
__device__ __forceinline__ void bargrp(int id) {
    asm volatile("bar.sync %0, 128;" :: "r"(id) : "memory");
}

// store single f16 h value at (element row e, A col k)
__device__ __forceinline__ void store_h16(char* sm, int buf, int e, int k, float v) {
    const int mt  = e >> 4, row = e & 15;
    const int kt  = k >> 4, kin = k & 15;
    const int tg  = (kin >> 1) & 3;
    const int ridx = ((row >= 8) ? 1 : 0) + ((kin >= 8) ? 2 : 0);
    const int lt   = (row & 7) * 4 + tg;
    const int base = buf * ABUF + (mt * 4 + kt) * 512 + lt * 16 + ridx * 4 + (k & 1) * 2;
    *(__half*)(sm + ABASE + base) = __float2half_rn(v);
}
// store f16x2 pair at cols (k, k+1), k even
__device__ __forceinline__ void store_hpair(char* sm, int buf, int e, int k,
                                            float v0, float v1) {
    const int mt  = e >> 4, row = e & 15;
    const int kt  = k >> 4, kin = k & 15;
    const int tg  = (kin >> 1) & 3;
    const int ridx = ((row >= 8) ? 1 : 0) + ((kin >= 8) ? 2 : 0);
    const int lt   = (row & 7) * 4 + tg;
    uint32_t hreg;
    asm("cvt.rn.f16x2.f32 %0, %1, %2;" : "=r"(hreg) : "f"(v1), "f"(v0));
    const int base = buf * ABUF + (mt * 4 + kt) * 512 + lt * 16 + ridx * 4;
    *(uint32_t*)(sm + ABASE + base) = hreg;
}

__global__ void __launch_bounds__(BLOCK, 1)
lstm_m32_kernel(const float* __restrict__ x_g,
                const float* __restrict__ wih_g,
                const float* __restrict__ whh_g,
                const float* __restrict__ bih_g,
                const float* __restrict__ bhh_g,
                const float* __restrict__ wlin_g,
                const float* __restrict__ blin_g,
                float* __restrict__ out_g)
{
    extern __shared__ char sm[];
    const int tid  = threadIdx.x;
    const int lane = tid & 31;
    const int wid  = tid >> 5;
    const int grp  = wid >> 2;          // 0..3: 32-element group
    const int q    = wid & 3;           // pair-quarter within group

    // ---- zero both A buffers ----
    for (int i = tid; i < (2 * ABUF) / 16; i += BLOCK)
        ((uint4*)(sm + ABASE))[i] = make_uint4(0, 0, 0, 0);

    // ---- build B fragments (single fp16) with gate-pair column order ----
    // nt even (pair p): cols = i,f of cells 4p..4p+3 ; nt odd: g,o
    for (int idx = tid; idx < NTT * 2 * 32; idx += BLOCK) {
        int r         = idx;
        const int nt  = r / 64;  r %= 64;
        const int kt2 = r / 32;
        const int ln  = r % 32;
        const int bgr = ln >> 2, btig = ln & 3;
        const int p    = nt >> 1, oddnt = nt & 1;
        const int u    = bgr >> 1, v = bgr & 1;
        const int cell = 4 * p + u;
        const int gate = oddnt ? (v ? 3 : 2) : (v ? 1 : 0);     // i,f | g,o
        const int grow = (gate == 0 ? 0 : gate == 1 ? 50 : gate == 2 ? 100 : 150);
        const int row  = grow + cell;
        const bool realc = (cell < HDIM);
        uint32_t u4[4];
#pragma unroll
        for (int ktl = 0; ktl < 2; ktl++) {
            const int kt = 2 * kt2 + ktl;
            const int kk[4] = {kt * 16 + 2 * btig,     kt * 16 + 2 * btig + 1,
                               kt * 16 + 2 * btig + 8, kt * 16 + 2 * btig + 9};
            unsigned short vv[4];
#pragma unroll
            for (int j = 0; j < 4; j++) {
                float w = 0.0f;
                const int k = kk[j];
                if (realc) {
                    if (k < HDIM)     w = whh_g[row * HDIM + k];
                    else if (k == 50) w = bih_g[row] + bhh_g[row];
                    else if (k == 51) w = wih_g[row];
                }
                vv[j] = __half_as_ushort(__float2half_rn(w));
            }
            u4[2 * ktl]     = ((uint32_t)vv[1] << 16) | vv[0];
            u4[2 * ktl + 1] = ((uint32_t)vv[3] << 16) | vv[2];
        }
        *(uint4*)(sm + BBASE + nt * 1024 + kt2 * 512 + ln * 16) =
            make_uint4(u4[0], u4[1], u4[2], u4[3]);
    }

    // ---- stage x and wlin ----
    {
        const float* xin = x_g + (size_t)blockIdx.x * ELPB * TSTEPS;
        for (int i = tid; i < ELPB * TSTEPS; i += BLOCK) {
            int el = i / TSTEPS, t = i % TSTEPS;
            ((float*)(sm + XBASE))[el * 61 + t] = xin[i];
        }
    }
    for (int i = tid; i < TSTEPS * HDIM; i += BLOCK)
        ((float*)(sm + WLBASE))[i] = wlin_g[i];
    __syncthreads();

    if (tid < ELPB)
        store_hpair(sm, 0, tid, 50, 1.0f, ((float*)(sm + XBASE))[tid * 61]);
    __syncthreads();

    // ---- lane roles ----
    const int gr  = lane >> 2;           // row group 0..7
    const int tig = lane & 3;            // cell-in-quad
    const int r0 = grp * 32 + gr;        // 4 rows per lane
    // rows: r0, r0+8 (mtile 2g), r0+16, r0+24 (mtile 2g+1)
    static const int pLoT[4]  = {0, 4, 7, 10};
    static const int pCntT[4] = {4, 3, 3, 3};
    const int pLo  = pLoT[q];
    const int pCnt = pCntT[q];
    const int barid = 1 + grp;

    float cst[16];
#pragma unroll
    for (int i = 0; i < 16; i++) cst[i] = 0.0f;
    float acc[4] = {0.0f, 0.0f, 0.0f, 0.0f};

    const float* xs = (const float*)(sm + XBASE);

    for (int t = 0; t < TSTEPS; t++) {
        const int cur = t & 1, nxt = cur ^ 1;

        // A fragments for BOTH m-tiles of the group
        uint32_t aH0[4][4], aH1[4][4];
        const char* ab0 = sm + ABASE + cur * ABUF + ((2 * grp) * 4) * 512 + lane * 16;
        const char* ab1 = ab0 + 4 * 512;
#pragma unroll
        for (int kt = 0; kt < 4; kt++) {
            *(uint4*)aH0[kt] = *(const uint4*)(ab0 + kt * 512);
            *(uint4*)aH1[kt] = *(const uint4*)(ab1 + kt * 512);
        }

        const float* wl = (const float*)(sm + WLBASE) + t * HDIM;

#pragma unroll
        for (int pp = 0; pp < 4; pp++) {
            if (pp >= pCnt) break;
            const int p    = pLo + pp;
            const int cell = 4 * p + tig;

            uint32_t bif[8], bgo[8];
            const char* bbE = sm + BBASE + (2 * p) * 1024 + lane * 16;
            *(uint4*)bif       = *(const uint4*)bbE;
            *(uint4*)(bif + 4) = *(const uint4*)(bbE + 512);
            *(uint4*)bgo       = *(const uint4*)(bbE + 1024);
            *(uint4*)(bgo + 4) = *(const uint4*)(bbE + 1536);

            float dif0[4] = {0, 0, 0, 0}, dif1[4] = {0, 0, 0, 0};
            float dgo0[4] = {0, 0, 0, 0}, dgo1[4] = {0, 0, 0, 0};
#pragma unroll
            for (int kt = 0; kt < 4; kt++) {
                mma16816h(dif0, aH0[kt], bif + 2 * kt);
                mma16816h(dif1, aH1[kt], bif + 2 * kt);
                mma16816h(dgo0, aH0[kt], bgo + 2 * kt);
                mma16816h(dgo1, aH1[kt], bgo + 2 * kt);
            }

            // rows r0, r0+8, r0+16, r0+24 : (i,f) from dif*, (g,o) from dgo*
            float gi[4], gf[4], gg[4], go[4];
            gi[0] = dif0[0]; gf[0] = dif0[1]; gg[0] = dgo0[0]; go[0] = dgo0[1];
            gi[1] = dif0[2]; gf[1] = dif0[3]; gg[1] = dgo0[2]; go[1] = dgo0[3];
            gi[2] = dif1[0]; gf[2] = dif1[1]; gg[2] = dgo1[0]; go[2] = dgo1[1];
            gi[3] = dif1[2]; gf[3] = dif1[3]; gg[3] = dgo1[2]; go[3] = dgo1[3];

            const bool realc = (cell < HDIM);
            const float wv = realc ? wl[cell] : 0.0f;
#pragma unroll
            for (int rr = 0; rr < 4; rr++) {
                const float iv = sigt(gi[rr]);
                const float fv = sigt(gf[rr]);
                const float ov = sigt(go[rr]);
                const float gv = tanha(gg[rr]);
                const int ci = pp * 4 + rr;
                cst[ci] = fmaf(fv, cst[ci], iv * gv);
                const float hv = ov * tanha(cst[ci]);
                acc[rr] = fmaf(hv, wv, acc[rr]);
                if (realc)
                    store_h16(sm, nxt, r0 + rr * 8, cell, hv);
            }
        }

        // refresh (1, x_{t+1}) in next buffer — warp q==3 of each group
        if (q == 3 && t + 1 < TSTEPS) {
            const int er = grp * 32 + lane;
            store_hpair(sm, nxt, er, 50, 1.0f, xs[er * 61 + t + 1]);
        }

        bargrp(barid);
    }

    // ---- reductions: over tig, then across the 4 warps of the group ----
#pragma unroll
    for (int rr = 0; rr < 4; rr++) {
        acc[rr] += __shfl_xor_sync(0xffffffffu, acc[rr], 1);
        acc[rr] += __shfl_xor_sync(0xffffffffu, acc[rr], 2);
    }
    float* op = (float*)(sm + OPBASE);
    if (tig == 0) {
#pragma unroll
        for (int rr = 0; rr < 4; rr++)
            op[q * ELPB + r0 + rr * 8] = acc[rr];
    }
    __syncthreads();
    if (tid < ELPB) {
        const float s = op[tid] + op[ELPB + tid] + op[2 * ELPB + tid] +
                        op[3 * ELPB + tid];
        out_g[(size_t)blockIdx.x * ELPB + tid] = s + blin_g[0];
    }
}

extern "C" void kernel_launch(void* const* d_in, const int* in_sizes, int n_in,
                              void* d_out, int out_size)
{
    const float* x    = (const float*)d_in[0];
    const float* wih  = (const float*)d_in[1];
    const float* whh  = (const float*)d_in[2];
    const float* bih  = (const float*)d_in[3];
    const float* bhh  = (const float*)d_in[4];
    const float* wlin = (const float*)d_in[5];
    const float* blin = (const float*)d_in[6];
    float* out = (float*)d_out;

    cudaFuncSetAttribute(lstm_m32_kernel,
                         cudaFuncAttributeMaxDynamicSharedMemorySize, SMTOT);
    lstm_m32_kernel<<<GRID, BLOCK, SMTOT>>>(x, wih, whh, bih, bhh, wlin, blin, out);
}

// round 13
// speedup vs baseline: 3.8761x; 1.0090x over previous
#include <cuda_runtime.h>
#include <cuda_fp16.h>
#include <cstdint>

#define TSTEPS 60
#define HDIM   50
#define BLOCK  512
#define ELPB   128
#define GRID   128
#define NTT    26                 // n-tiles (13 pairs x 16 gate cols)

// ---- smem byte layout ----
#define ABASE  0
#define ABUF   16384               // per buffer: 8 mt x 4 kt x 512B (fp16)
#define BBASE  (2 * ABUF)          // 32768  (single split, 26624 B)
#define XBASE  (BBASE + NTT * 1024)          // 59392
#define WLBASE (XBASE + ELPB * 61 * 4)       // 90624
#define OPBASE (WLBASE + TSTEPS * HDIM * 4)  // 102624
#define SMTOT  (OPBASE + 4 * ELPB * 4)       // 104672

#define H05 0x38003800u            // f16x2 (0.5, 0.5)

__device__ __forceinline__ float tanha(float x) {
    float r; asm("tanh.approx.f32 %0, %1;" : "=f"(r) : "f"(x)); return r;
}
__device__ __forceinline__ float sigt(float x) {
    return fmaf(0.5f, tanha(0.5f * x), 0.5f);
}
__device__ __forceinline__ uint32_t pk2(float lo, float hi) {
    uint32_t r; asm("cvt.rn.f16x2.f32 %0, %1, %2;" : "=r"(r) : "f"(hi), "f"(lo));
    return r;
}
__device__ __forceinline__ uint32_t th2(uint32_t x) {
    uint32_t r; asm("tanh.approx.f16x2 %0, %1;" : "=r"(r) : "r"(x)); return r;
}
__device__ __forceinline__ uint32_t hmul2(uint32_t a, uint32_t b) {
    uint32_t r; asm("mul.f16x2 %0, %1, %2;" : "=r"(r) : "r"(a), "r"(b)); return r;
}
__device__ __forceinline__ uint32_t hfma2(uint32_t a, uint32_t b, uint32_t c) {
    uint32_t r; asm("fma.rn.f16x2 %0, %1, %2, %3;" : "=r"(r) : "r"(a), "r"(b), "r"(c));
    return r;
}
__device__ __forceinline__ uint32_t sig2(uint32_t x) {
    return hfma2(th2(hmul2(x, H05)), H05, H05);
}
__device__ __forceinline__ void up2(uint32_t h, float& lo, float& hi) {
    asm("{\n\t.reg .b16 l, h;\n\tmov.b32 {l, h}, %2;\n\t"
        "cvt.f32.f16 %0, l;\n\tcvt.f32.f16 %1, h;\n\t}"
        : "=f"(lo), "=f"(hi) : "r"(h));
}
__device__ __forceinline__ void mma16816h(float* d, const uint32_t* a, const uint32_t* b) {
    asm volatile(
        "mma.sync.aligned.m16n8k16.row.col.f32.f16.f16.f32 "
        "{%0,%1,%2,%3}, {%4,%5,%6,%7}, {%8,%9}, {%0,%1,%2,%3};"
        : "+f"(d[0]), "+f"(d[1]), "+f"(d[2]), "+f"(d[3])
        : "r"(a[0]), "r"(a[1]), "r"(a[2]), "r"(a[3]), "r"(b[0]), "r"(b[1]));
}
__device__ __forceinline__ void bargrp(int id) {
    asm volatile("bar.sync %0, 128;" :: "r"(id) : "memory");
}

// store h2 = (h(row gr), h(row gr+8)) of m-tile mt at A col k
__device__ __forceinline__ void store_h2pair(char* sm, int buf, int mt, int gr,
                                             int k, uint32_t h2) {
    const int kt = k >> 4, kin = k & 15;
    const int tg = (kin >> 1) & 3;
    const int base = buf * ABUF + (mt * 4 + kt) * 512 + (gr * 4 + tg) * 16 +
                     ((kin >= 8) ? 8 : 0) + (k & 1) * 2;
    *(uint16_t*)(sm + ABASE + base)     = (uint16_t)h2;
    *(uint16_t*)(sm + ABASE + base + 4) = (uint16_t)(h2 >> 16);
}
// store f16x2 pair at cols (k, k+1) of element row e, k even
__device__ __forceinline__ void store_hpair(char* sm, int buf, int e, int k,
                                            float v0, float v1) {
    const int mt  = e >> 4, row = e & 15;
    const int kt  = k >> 4, kin = k & 15;
    const int tg  = (kin >> 1) & 3;
    const int ridx = ((row >= 8) ? 1 : 0) + ((kin >= 8) ? 2 : 0);
    const int lt   = (row & 7) * 4 + tg;
    const uint32_t hreg = pk2(v0, v1);
    const int base = buf * ABUF + (mt * 4 + kt) * 512 + lt * 16 + ridx * 4;
    *(uint32_t*)(sm + ABASE + base) = hreg;
}

// the whole recurrence, specialized on pair count for straight-line code
template<int PCNT>
__device__ __forceinline__ void run_steps(char* sm, const float* xs,
                                          int grp, int lane, int pLo,
                                          int barid, bool doX, float* acc)
{
    const int gr  = lane >> 2;
    const int tig = lane & 3;
    const int mt0 = 2 * grp, mt1 = 2 * grp + 1;

    float cst[PCNT * 4];
#pragma unroll
    for (int i = 0; i < PCNT * 4; i++) cst[i] = 0.0f;

    for (int t = 0; t < TSTEPS; t++) {
        const int cur = t & 1, nxt = cur ^ 1;

        uint32_t aH0[4][4], aH1[4][4];
        const char* ab0 = sm + ABASE + cur * ABUF + (mt0 * 4) * 512 + lane * 16;
        const char* ab1 = ab0 + 4 * 512;
#pragma unroll
        for (int kt = 0; kt < 4; kt++) {
            *(uint4*)aH0[kt] = *(const uint4*)(ab0 + kt * 512);
            *(uint4*)aH1[kt] = *(const uint4*)(ab1 + kt * 512);
        }

        const float* wl = (const float*)(sm + WLBASE) + t * HDIM;

#pragma unroll
        for (int pp = 0; pp < PCNT; pp++) {
            const int p    = pLo + pp;
            const int cell = 4 * p + tig;

            uint32_t bif[8], bgo[8];
            const char* bbE = sm + BBASE + (2 * p) * 1024 + lane * 16;
            *(uint4*)bif       = *(const uint4*)bbE;
            *(uint4*)(bif + 4) = *(const uint4*)(bbE + 512);
            *(uint4*)bgo       = *(const uint4*)(bbE + 1024);
            *(uint4*)(bgo + 4) = *(const uint4*)(bbE + 1536);

            float dif0[4] = {0, 0, 0, 0}, dif1[4] = {0, 0, 0, 0};
            float dgo0[4] = {0, 0, 0, 0}, dgo1[4] = {0, 0, 0, 0};
#pragma unroll
            for (int kt = 0; kt < 4; kt++) {
                mma16816h(dif0, aH0[kt], bif + 2 * kt);
                mma16816h(dif1, aH1[kt], bif + 2 * kt);
                mma16816h(dgo0, aH0[kt], bgo + 2 * kt);
                mma16816h(dgo1, aH1[kt], bgo + 2 * kt);
            }

            const bool realc = (cell < HDIM);
            const float wv = realc ? wl[cell] : 0.0f;
            const int ci = pp * 4;

            // ---- rows (gr, gr+8) of m-tile mt0 ----
            {
                const float iv0 = sigt(dif0[0]), iv1 = sigt(dif0[2]);
                const float fv0 = sigt(dif0[1]), fv1 = sigt(dif0[3]);
                const float gv0 = tanha(dgo0[0]), gv1 = tanha(dgo0[2]);
                cst[ci]     = fmaf(fv0, cst[ci],     iv0 * gv0);
                cst[ci + 1] = fmaf(fv1, cst[ci + 1], iv1 * gv1);
                const uint32_t o2 = sig2(pk2(dgo0[1], dgo0[3]));
                const uint32_t h2 = hmul2(o2, th2(pk2(cst[ci], cst[ci + 1])));
                float hl, hh;
                up2(h2, hl, hh);
                acc[0] = fmaf(hl, wv, acc[0]);
                acc[1] = fmaf(hh, wv, acc[1]);
                if (realc) store_h2pair(sm, nxt, mt0, gr, cell, h2);
            }
            // ---- rows (gr+16, gr+24) of m-tile mt1 ----
            {
                const float iv0 = sigt(dif1[0]), iv1 = sigt(dif1[2]);
                const float fv0 = sigt(dif1[1]), fv1 = sigt(dif1[3]);
                const float gv0 = tanha(dgo1[0]), gv1 = tanha(dgo1[2]);
                cst[ci + 2] = fmaf(fv0, cst[ci + 2], iv0 * gv0);
                cst[ci + 3] = fmaf(fv1, cst[ci + 3], iv1 * gv1);
                const uint32_t o2 = sig2(pk2(dgo1[1], dgo1[3]));
                const uint32_t h2 = hmul2(o2, th2(pk2(cst[ci + 2], cst[ci + 3])));
                float hl, hh;
                up2(h2, hl, hh);
                acc[2] = fmaf(hl, wv, acc[2]);
                acc[3] = fmaf(hh, wv, acc[3]);
                if (realc) store_h2pair(sm, nxt, mt1, gr, cell, h2);
            }
        }

        if (doX && t + 1 < TSTEPS) {
            const int er = grp * 32 + lane;
            store_hpair(sm, nxt, er, 50, 1.0f, xs[er * 61 + t + 1]);
        }

        bargrp(barid);
    }
}

__global__ void __launch_bounds__(BLOCK, 1)
lstm_u_kernel(const float* __restrict__ x_g,
              const float* __restrict__ wih_g,
              const float* __restrict__ whh_g,
              const float* __restrict__ bih_g,
              const float* __restrict__ bhh_g,
              const float* __restrict__ wlin_g,
              const float* __restrict__ blin_g,
              float* __restrict__ out_g)
{
    extern __shared__ char sm[];
    const int tid  = threadIdx.x;
    const int lane = tid & 31;
    const int wid  = tid >> 5;
    const int grp  = wid >> 2;
    const int q    = wid & 3;

    // ---- zero both A buffers ----
    for (int i = tid; i < (2 * ABUF) / 16; i += BLOCK)
        ((uint4*)(sm + ABASE))[i] = make_uint4(0, 0, 0, 0);

    // ---- build B fragments (fp16) with gate-pair column order ----
    for (int idx = tid; idx < NTT * 2 * 32; idx += BLOCK) {
        int r         = idx;
        const int nt  = r / 64;  r %= 64;
        const int kt2 = r / 32;
        const int ln  = r % 32;
        const int bgr = ln >> 2, btig = ln & 3;
        const int p    = nt >> 1, oddnt = nt & 1;
        const int u    = bgr >> 1, v = bgr & 1;
        const int cell = 4 * p + u;
        const int gate = oddnt ? (v ? 3 : 2) : (v ? 1 : 0);     // i,f | g,o
        const int grow = (gate == 0 ? 0 : gate == 1 ? 50 : gate == 2 ? 100 : 150);
        const int row  = grow + cell;
        const bool realc = (cell < HDIM);
        uint32_t u4[4];
#pragma unroll
        for (int ktl = 0; ktl < 2; ktl++) {
            const int kt = 2 * kt2 + ktl;
            const int kk[4] = {kt * 16 + 2 * btig,     kt * 16 + 2 * btig + 1,
                               kt * 16 + 2 * btig + 8, kt * 16 + 2 * btig + 9};
            unsigned short vv[4];
#pragma unroll
            for (int j = 0; j < 4; j++) {
                float w = 0.0f;
                const int k = kk[j];
                if (realc) {
                    if (k < HDIM)     w = whh_g[row * HDIM + k];
                    else if (k == 50) w = bih_g[row] + bhh_g[row];
                    else if (k == 51) w = wih_g[row];
                }
                vv[j] = __half_as_ushort(__float2half_rn(w));
            }
            u4[2 * ktl]     = ((uint32_t)vv[1] << 16) | vv[0];
            u4[2 * ktl + 1] = ((uint32_t)vv[3] << 16) | vv[2];
        }
        *(uint4*)(sm + BBASE + nt * 1024 + kt2 * 512 + ln * 16) =
            make_uint4(u4[0], u4[1], u4[2], u4[3]);
    }

    // ---- stage x and wlin ----
    {
        const float* xin = x_g + (size_t)blockIdx.x * ELPB * TSTEPS;
        for (int i = tid; i < ELPB * TSTEPS; i += BLOCK) {
            int el = i / TSTEPS, t = i % TSTEPS;
            ((float*)(sm + XBASE))[el * 61 + t] = xin[i];
        }
    }
    for (int i = tid; i < TSTEPS * HDIM; i += BLOCK)
        ((float*)(sm + WLBASE))[i] = wlin_g[i];
    __syncthreads();

    if (tid < ELPB)
        store_hpair(sm, 0, tid, 50, 1.0f, ((float*)(sm + XBASE))[tid * 61]);
    __syncthreads();

    static const int pLoT[4] = {0, 4, 7, 10};
    const int pLo  = pLoT[q];
    const int barid = 1 + grp;
    const float* xs = (const float*)(sm + XBASE);

    float acc[4] = {0.0f, 0.0f, 0.0f, 0.0f};
    if (q == 0)
        run_steps<4>(sm, xs, grp, lane, pLo, barid, false, acc);
    else
        run_steps<3>(sm, xs, grp, lane, pLo, barid, q == 3, acc);

    // ---- reductions: over tig, then across the 4 warps of the group ----
    const int gr = lane >> 2;
    const int tig = lane & 3;
    const int r0 = grp * 32 + gr;
#pragma unroll
    for (int rr = 0; rr < 4; rr++) {
        acc[rr] += __shfl_xor_sync(0xffffffffu, acc[rr], 1);
        acc[rr] += __shfl_xor_sync(0xffffffffu, acc[rr], 2);
    }
    float* op = (float*)(sm + OPBASE);
    if (tig == 0) {
#pragma unroll
        for (int rr = 0; rr < 4; rr++)
            op[q * ELPB + r0 + rr * 8] = acc[rr];
    }
    __syncthreads();
    if (tid < ELPB) {
        const float s = op[tid] + op[ELPB + tid] + op[2 * ELPB + tid] +
                        op[3 * ELPB + tid];
        out_g[(size_t)blockIdx.x * ELPB + tid] = s + blin_g[0];
    }
}

extern "C" void kernel_launch(void* const* d_in, const int* in_sizes, int n_in,
                              void* d_out, int out_size)
{
    const float* x    = (const float*)d_in[0];
    const float* wih  = (const float*)d_in[1];
    const float* whh  = (const float*)d_in[2];
    const float* bih  = (const float*)d_in[3];
    const float* bhh  = (const float*)d_in[4];
    const float* wlin = (const float*)d_in[5];
    const float* blin = (const float*)d_in[6];
    float* out = (float*)d_out;

    cudaFuncSetAttribute(lstm_u_kernel,
                         cudaFuncAttributeMaxDynamicSharedMemorySize, SMTOT);
    lstm_u_kernel<<<GRID, BLOCK, SMTOT>>>(x, wih, whh, bih, bhh, wlin, blin, out);
}